// round 11
// baseline (speedup 1.0000x reference)
#include <cuda_runtime.h>
#include <cuda_fp16.h>

constexpr int N   = 100000;
constexpr int E   = 3200000;
constexpr int FIN = 512;
constexpr int SCAN_BLOCKS = 98;               // ceil(N/1024)
constexpr int GB  = 391;                      // gemm blocks, 256 rows each
constexpr int SBK = 201;                      // scatter blocks
constexpr int GRID2 = GB + SBK;               // 592 = 4 * 148
constexpr int XS_STRIDE = 12;                 // floats per staged row (8 used + pad)
constexpr int SMEM_FLOATS = 8192 + 256 * XS_STRIDE;
constexpr int SMEM_BYTES  = SMEM_FLOATS * 4;  // 45056

// scratch (zero-init at load; self-cleaned every run)
__device__ int    g_cnt[N];            // zeroed by k_scan after reading
__device__ int    g_aggA[SCAN_BLOCKS];
__device__ int    g_ready;             // reset by k_hist each run
__device__ int    g_rowptr[N + 1];
__device__ int    g_cur[N];
__device__ int    g_csrc[E];
__device__ float  g_dinv[N];
__device__ __align__(16) uint2 g_h1h[N * 4];  // fp16 rows: h1 * dinv[row]
__device__ __align__(16) uint2 g_rsh[N * 4];  // fp16 rows: relu(l1)*dinv

__device__ __forceinline__ void ffma2(unsigned long long& d,
                                      unsigned long long a,
                                      unsigned long long b) {
    asm("fma.rn.f32x2 %0, %1, %2, %0;" : "+l"(d) : "l"(a), "l"(b));
}
__device__ __forceinline__ unsigned long long bcast2(float v) {
    unsigned long long r;
    asm("mov.b64 %0, {%1, %1};" : "=l"(r) : "f"(v));
    return r;
}
__device__ __forceinline__ float2 unpack2(unsigned long long v) {
    float2 r;
    asm("mov.b64 {%0, %1}, %2;" : "=f"(r.x), "=f"(r.y) : "l"(v));
    return r;
}
__device__ __forceinline__ float4 h4_to_f4(uint2 hv) {
    __half2 a = *reinterpret_cast<__half2*>(&hv.x);
    __half2 b = *reinterpret_cast<__half2*>(&hv.y);
    float2 fa = __half22float2(a);
    float2 fb = __half22float2(b);
    return make_float4(fa.x, fa.y, fb.x, fb.y);
}
__device__ __forceinline__ uint2 pack_h4(float a, float b, float c, float d) {
    __half2 lo = __floats2half2_rn(a, b);
    __half2 hi = __floats2half2_rn(c, d);
    uint2 r;
    r.x = *reinterpret_cast<unsigned*>(&lo);
    r.y = *reinterpret_cast<unsigned*>(&hi);
    return r;
}

// ================= k_hist =================
__global__ void k_hist(const int* __restrict__ ei) {
    if (blockIdx.x == 0 && threadIdx.x == 0) g_ready = 0;
    int i = blockIdx.x * blockDim.x + threadIdx.x;   // exactly E/4 threads
    const int4* d4 = (const int4*)(ei + E);
    int4 d = __ldg(&d4[i]);
    atomicAdd(&g_cnt[d.x], 1);
    atomicAdd(&g_cnt[d.y], 1);
    atomicAdd(&g_cnt[d.z], 1);
    atomicAdd(&g_cnt[d.w], 1);
}

// ================= k_scan =================
__global__ void k_scan() {
    __shared__ int sh[256];
    __shared__ int s_base;
    const int b = blockIdx.x, t = threadIdx.x;
    const int i0 = b * 1024 + t * 4;

    int v0 = (i0 + 0 < N) ? __ldcg(&g_cnt[i0 + 0]) : 0;
    int v1 = (i0 + 1 < N) ? __ldcg(&g_cnt[i0 + 1]) : 0;
    int v2 = (i0 + 2 < N) ? __ldcg(&g_cnt[i0 + 2]) : 0;
    int v3 = (i0 + 3 < N) ? __ldcg(&g_cnt[i0 + 3]) : 0;
    int tot = v0 + v1 + v2 + v3;

    sh[t] = tot;
    if (t == 0) s_base = 0;
    __syncthreads();
#pragma unroll
    for (int o = 1; o < 256; o <<= 1) {
        int a = (t >= o) ? sh[t - o] : 0;
        __syncthreads();
        sh[t] += a;
        __syncthreads();
    }
    int incl = sh[t];
    if (t == 255) {
        g_aggA[b] = incl;
        __threadfence();
        atomicAdd(&g_ready, 1);
    }
    if (t == 0) {
        while (__ldcg((const int*)&g_ready) < SCAN_BLOCKS) __nanosleep(32);
    }
    __syncthreads();
    if (t < b) atomicAdd(&s_base, __ldcg(&g_aggA[t]));
    __syncthreads();

    int e0 = s_base + incl - tot;
    int pre[4] = {e0, e0 + v0, e0 + v0 + v1, e0 + v0 + v1 + v2};
    int vv[4]  = {v0, v1, v2, v3};
#pragma unroll
    for (int u = 0; u < 4; ++u) {
        int i = i0 + u;
        if (i < N) {
            g_rowptr[i] = pre[u];
            g_cur[i]    = pre[u];
            g_dinv[i]   = rsqrtf((float)(vv[u] + 1));
            g_cnt[i]    = 0;
        }
    }
    if (b == 0 && t == 0) g_rowptr[N] = E;
}

// ====== k2: register-tiled GEMM (4 rows x 8 cols / thread, LDG prefetch) || scatter ======
__global__ void __launch_bounds__(128, 4) k2(
    const float* __restrict__ x, const float* __restrict__ W1,
    const int* __restrict__ ei)
{
    extern __shared__ float sm[];
    const int t = threadIdx.x, bid = blockIdx.x;

    if (bid < GB) {
        // stage W1 (512x16 fp32 = 32 KB)
        const float4* w4 = (const float4*)W1;
        float4* s4 = (float4*)sm;
#pragma unroll
        for (int i = 0; i < 16; ++i) s4[i * 128 + t] = __ldg(&w4[i * 128 + t]);

        float* xs = sm + 8192;                 // 256 rows x XS_STRIDE
        const int row0 = bid * 256;
        const int c  = t & 1;                  // col half: cols c*8 .. c*8+7
        const int rg = t >> 1;                 // 0..63; rows rg + 64*j

        // fixed per-p base pointers for the staging loads
        const float* xb[4];
        int srow[4], shalf[4];
#pragma unroll
        for (int p = 0; p < 4; ++p) {
            int idx = p * 128 + t;
            srow[p] = idx >> 1; shalf[p] = idx & 1;
            int gr = row0 + srow[p]; if (gr >= N) gr = N - 1;
            xb[p] = x + (size_t)gr * FIN + shalf[p] * 4;
        }

        unsigned long long acc[4][4];
#pragma unroll
        for (int j = 0; j < 4; ++j)
#pragma unroll
            for (int p = 0; p < 4; ++p) acc[j][p] = 0ull;

        float4 pf[4];
#pragma unroll
        for (int p = 0; p < 4; ++p) pf[p] = __ldg((const float4*)(xb[p]));

        for (int kt = 0; kt < 64; ++kt) {
            __syncthreads();                    // prev compute done; smem reusable
#pragma unroll
            for (int p = 0; p < 4; ++p)
                *(float4*)(xs + srow[p] * XS_STRIDE + shalf[p] * 4) = pf[p];
            __syncthreads();
            if (kt < 63) {
#pragma unroll
                for (int p = 0; p < 4; ++p)
                    pf[p] = __ldg((const float4*)(xb[p] + (kt + 1) * 8));
            }
#pragma unroll
            for (int kh = 0; kh < 2; ++kh) {
                float xq[4][4];
#pragma unroll
                for (int j = 0; j < 4; ++j) {
                    float4 v = *(const float4*)(xs + (rg + 64 * j) * XS_STRIDE + kh * 4);
                    xq[j][0] = v.x; xq[j][1] = v.y; xq[j][2] = v.z; xq[j][3] = v.w;
                }
#pragma unroll
                for (int kk = 0; kk < 4; ++kk) {
                    int k = kt * 8 + kh * 4 + kk;
                    ulonglong2 w0 = *(const ulonglong2*)(sm + k * 16 + c * 8);
                    ulonglong2 w1 = *(const ulonglong2*)(sm + k * 16 + c * 8 + 4);
#pragma unroll
                    for (int j = 0; j < 4; ++j) {
                        unsigned long long b = bcast2(xq[j][kk]);
                        ffma2(acc[j][0], b, w0.x); ffma2(acc[j][1], b, w0.y);
                        ffma2(acc[j][2], b, w1.x); ffma2(acc[j][3], b, w1.y);
                    }
                }
            }
        }
        // epilogue: scale by dinv, pack fp16, store 8 cols (16B) per row
#pragma unroll
        for (int j = 0; j < 4; ++j) {
            int row = row0 + rg + 64 * j;
            if (row < N) {
                float dv = g_dinv[row];
                float2 p0 = unpack2(acc[j][0]), p1 = unpack2(acc[j][1]);
                float2 p2 = unpack2(acc[j][2]), p3 = unpack2(acc[j][3]);
                uint2 lo = pack_h4(p0.x * dv, p0.y * dv, p1.x * dv, p1.y * dv);
                uint2 hi = pack_h4(p2.x * dv, p2.y * dv, p3.x * dv, p3.y * dv);
                ((uint4*)&g_h1h[(size_t)row * 4])[c] = make_uint4(lo.x, lo.y, hi.x, hi.y);
            }
        }
    } else {
        // scatter: fill CSR adjacency
        const int4* s4 = (const int4*)ei;
        const int4* d4 = (const int4*)(ei + E);
        const int nthr = SBK * 128;
        for (int i = (bid - GB) * 128 + t; i < E / 4; i += nthr) {
            int4 s = __ldg(&s4[i]);
            int4 d = __ldg(&d4[i]);
            g_csrc[atomicAdd(&g_cur[d.x], 1)] = s.x;
            g_csrc[atomicAdd(&g_cur[d.y], 1)] = s.y;
            g_csrc[atomicAdd(&g_cur[d.z], 1)] = s.z;
            g_csrc[atomicAdd(&g_cur[d.w], 1)] = s.w;
        }
    }
}

// ================= pair gather =================
__device__ __forceinline__ void gather_pair(const uint2* __restrict__ h,
                                            int sA, int eA, int eB,
                                            int lane, int slot, int q,
                                            float4& A, float4& B) {
    A = make_float4(0.f, 0.f, 0.f, 0.f);
    B = make_float4(0.f, 0.f, 0.f, 0.f);
    for (int base = sA; base < eB; base += 32) {
        int e = base + lane;
        int s = (e < eB) ? __ldg(&g_csrc[e]) : 0;
#pragma unroll
        for (int j = 0; j < 32; j += 8) {
            int jj = j + slot;
            int ee = base + jj;
            int sj = __shfl_sync(0xffffffffu, s, jj);
            if (ee < eB) {
                float4 v = h4_to_f4(__ldg(&h[(size_t)sj * 4 + q]));
                if (ee < eA) {
                    A.x += v.x; A.y += v.y; A.z += v.z; A.w += v.w;
                } else {
                    B.x += v.x; B.y += v.y; B.z += v.z; B.w += v.w;
                }
            }
        }
    }
#pragma unroll
    for (int o = 4; o < 32; o <<= 1) {
        A.x += __shfl_xor_sync(0xffffffffu, A.x, o);
        A.y += __shfl_xor_sync(0xffffffffu, A.y, o);
        A.z += __shfl_xor_sync(0xffffffffu, A.z, o);
        A.w += __shfl_xor_sync(0xffffffffu, A.w, o);
        B.x += __shfl_xor_sync(0xffffffffu, B.x, o);
        B.y += __shfl_xor_sync(0xffffffffu, B.y, o);
        B.z += __shfl_xor_sync(0xffffffffu, B.z, o);
        B.w += __shfl_xor_sync(0xffffffffu, B.w, o);
    }
}

// layer-1 epilogue (trivial now): rs = relu((acc+self)*dinv + b1) * dinv
__device__ __forceinline__ uint2 epi1s(int node, float4 acc, float4 b1q, int q) {
    float dv = g_dinv[node];
    float4 sv = h4_to_f4(g_h1h[(size_t)node * 4 + q]);
    float rx = fmaxf((acc.x + sv.x) * dv + b1q.x, 0.f);
    float ry = fmaxf((acc.y + sv.y) * dv + b1q.y, 0.f);
    float rz = fmaxf((acc.z + sv.z) * dv + b1q.z, 0.f);
    float rw = fmaxf((acc.w + sv.w) * dv + b1q.w, 0.f);
    return pack_h4(rx * dv, ry * dv, rz * dv, rw * dv);
}

// ================= agg1 =================
__global__ void __launch_bounds__(256) k_agg1(const float* __restrict__ b1) {
    const int t = threadIdx.x;
    const int wid = (int)((blockIdx.x * blockDim.x + t) >> 5);
    const int nA = wid * 2;
    const int lane = t & 31, slot = lane >> 2, q = lane & 3;
    const float4 b1q = __ldg(&((const float4*)b1)[q]);

    const int sA = __ldg(&g_rowptr[nA]);
    const int eA = __ldg(&g_rowptr[nA + 1]);
    const int eB = __ldg(&g_rowptr[nA + 2]);

    float4 accA, accB;
    gather_pair(g_h1h, sA, eA, eB, lane, slot, q, accA, accB);

    uint2 oA = epi1s(nA, accA, b1q, q);
    if (slot == 0) g_rsh[(size_t)nA * 4 + q] = oA;
    uint2 oB = epi1s(nA + 1, accB, b1q, q);
    if (slot == 1) g_rsh[(size_t)(nA + 1) * 4 + q] = oB;
}

// layer-2 epilogue: apply W2 AFTER gather (linearity), + b2, log_softmax
__device__ __forceinline__ float4 epi2w(int node, float4 acc, float4 b2q,
                                        const float4* w2s, int q) {
    float dv = g_dinv[node];
    float4 sv = h4_to_f4(g_rsh[(size_t)node * 4 + q]);
    float4 a;
    a.x = acc.x + sv.x; a.y = acc.y + sv.y;
    a.z = acc.z + sv.z; a.w = acc.w + sv.w;

    float4 h2 = make_float4(0.f, 0.f, 0.f, 0.f);
#pragma unroll
    for (int qq = 0; qq < 4; ++qq) {
        float ax = __shfl_sync(0xffffffffu, a.x, qq, 4);
        float ay = __shfl_sync(0xffffffffu, a.y, qq, 4);
        float az = __shfl_sync(0xffffffffu, a.z, qq, 4);
        float aw = __shfl_sync(0xffffffffu, a.w, qq, 4);
        float4 w0 = w2s[(qq * 4 + 0) * 4 + q];
        float4 w1 = w2s[(qq * 4 + 1) * 4 + q];
        float4 w2v = w2s[(qq * 4 + 2) * 4 + q];
        float4 w3 = w2s[(qq * 4 + 3) * 4 + q];
        h2.x = fmaf(ax, w0.x, fmaf(ay, w1.x, fmaf(az, w2v.x, fmaf(aw, w3.x, h2.x))));
        h2.y = fmaf(ax, w0.y, fmaf(ay, w1.y, fmaf(az, w2v.y, fmaf(aw, w3.y, h2.y))));
        h2.z = fmaf(ax, w0.z, fmaf(ay, w1.z, fmaf(az, w2v.z, fmaf(aw, w3.z, h2.z))));
        h2.w = fmaf(ax, w0.w, fmaf(ay, w1.w, fmaf(az, w2v.w, fmaf(aw, w3.w, h2.w))));
    }
    float4 val;
    val.x = h2.x * dv + b2q.x;
    val.y = h2.y * dv + b2q.y;
    val.z = h2.z * dv + b2q.z;
    val.w = h2.w * dv + b2q.w;

    float m = fmaxf(fmaxf(val.x, val.y), fmaxf(val.z, val.w));
    m = fmaxf(m, __shfl_xor_sync(0xffffffffu, m, 1));
    m = fmaxf(m, __shfl_xor_sync(0xffffffffu, m, 2));
    float ssum = __expf(val.x - m) + __expf(val.y - m) +
                 __expf(val.z - m) + __expf(val.w - m);
    ssum += __shfl_xor_sync(0xffffffffu, ssum, 1);
    ssum += __shfl_xor_sync(0xffffffffu, ssum, 2);
    float lse = m + __logf(ssum);
    return make_float4(val.x - lse, val.y - lse, val.z - lse, val.w - lse);
}

// ================= agg2 =================
__global__ void __launch_bounds__(256) k_agg2(const float* __restrict__ b2,
                                              const float* __restrict__ W2,
                                              float* __restrict__ out) {
    __shared__ float4 w2s[64];
    const int t = threadIdx.x;
    if (t < 64) w2s[t] = __ldg(&((const float4*)W2)[t]);
    __syncthreads();

    const int wid = (int)((blockIdx.x * blockDim.x + t) >> 5);
    const int nA = wid * 2;
    const int lane = t & 31, slot = lane >> 2, q = lane & 3;
    const float4 b2q = __ldg(&((const float4*)b2)[q]);

    const int sA = __ldg(&g_rowptr[nA]);
    const int eA = __ldg(&g_rowptr[nA + 1]);
    const int eB = __ldg(&g_rowptr[nA + 2]);

    float4 accA, accB;
    gather_pair(g_rsh, sA, eA, eB, lane, slot, q, accA, accB);

    float4 oA = epi2w(nA, accA, b2q, w2s, q);
    if (slot == 0) ((float4*)out)[(size_t)nA * 4 + q] = oA;
    float4 oB = epi2w(nA + 1, accB, b2q, w2s, q);
    if (slot == 1) ((float4*)out)[(size_t)(nA + 1) * 4 + q] = oB;
}

// ================= launch =================
extern "C" void kernel_launch(void* const* d_in, const int* in_sizes, int n_in,
                              void* d_out, int out_size) {
    const float* x  = (const float*)d_in[0];
    const float* W1 = (const float*)d_in[1];
    const float* b1 = (const float*)d_in[2];
    const float* W2 = (const float*)d_in[3];
    const float* b2 = (const float*)d_in[4];
    const int*   ei = (const int*)d_in[5];
    float* out = (float*)d_out;

    cudaFuncSetAttribute((const void*)k2,
                         cudaFuncAttributeMaxDynamicSharedMemorySize, SMEM_BYTES);

    k_hist<<<E / 4 / 256, 256>>>(ei);
    k_scan<<<SCAN_BLOCKS, 256>>>();
    k2    <<<GRID2, 128, SMEM_BYTES>>>(x, W1, ei);
    k_agg1<<<N / 2 / 8, 256>>>(b1);
    k_agg2<<<N / 2 / 8, 256>>>(b2, W2, out);
}

// round 12
// speedup vs baseline: 1.3162x; 1.3162x over previous
#include <cuda_runtime.h>
#include <cuda_fp16.h>

constexpr int N   = 100000;
constexpr int E   = 3200000;
constexpr int FIN = 512;
constexpr int SCAN_BLOCKS = 98;               // ceil(N/1024)
constexpr int GB  = 391;                      // gemm blocks, 256 rows each
constexpr int SBK = 201;                      // scatter blocks
constexpr int GRID2 = GB + SBK;               // 592 = 4 * 148
constexpr int XS_STRIDE = 12;                 // floats per staged row (8 used + pad)
constexpr int SMEM_FLOATS = 8192 + 256 * XS_STRIDE;
constexpr int SMEM_BYTES  = SMEM_FLOATS * 4;  // 45056

// scratch (zero-init at load; self-cleaned every run)
__device__ int    g_cnt[N];            // zeroed by k_scan after reading
__device__ int    g_aggA[SCAN_BLOCKS];
__device__ int    g_ready;             // reset by k_hist each run
__device__ int    g_rowptr[N + 1];
__device__ int    g_cur[N];
__device__ int    g_csrc[E];
__device__ float  g_dinv[N];
__device__ __align__(16) uint2 g_h1h[N * 4];   // fp16: h1 * dinv[row]
__device__ __align__(16) uint2 g_rsh[N * 4];   // fp16: relu(l1) * dinv[row]
__device__ __align__(16) uint2 g_rs2h[N * 4];  // fp16: (W2^T rs) rows

__device__ __forceinline__ void ffma2(unsigned long long& d,
                                      unsigned long long a,
                                      unsigned long long b) {
    asm("fma.rn.f32x2 %0, %1, %2, %0;" : "+l"(d) : "l"(a), "l"(b));
}
__device__ __forceinline__ unsigned long long bcast2(float v) {
    unsigned long long r;
    asm("mov.b64 %0, {%1, %1};" : "=l"(r) : "f"(v));
    return r;
}
__device__ __forceinline__ float2 unpack2(unsigned long long v) {
    float2 r;
    asm("mov.b64 {%0, %1}, %2;" : "=f"(r.x), "=f"(r.y) : "l"(v));
    return r;
}
__device__ __forceinline__ float4 h4_to_f4(uint2 hv) {
    __half2 a = *reinterpret_cast<__half2*>(&hv.x);
    __half2 b = *reinterpret_cast<__half2*>(&hv.y);
    float2 fa = __half22float2(a);
    float2 fb = __half22float2(b);
    return make_float4(fa.x, fa.y, fb.x, fb.y);
}
__device__ __forceinline__ uint2 pack_h4(float a, float b, float c, float d) {
    __half2 lo = __floats2half2_rn(a, b);
    __half2 hi = __floats2half2_rn(c, d);
    uint2 r;
    r.x = *reinterpret_cast<unsigned*>(&lo);
    r.y = *reinterpret_cast<unsigned*>(&hi);
    return r;
}

// ================= k_hist =================
__global__ void k_hist(const int* __restrict__ ei) {
    if (blockIdx.x == 0 && threadIdx.x == 0) g_ready = 0;
    int i = blockIdx.x * blockDim.x + threadIdx.x;   // exactly E/4 threads
    const int4* d4 = (const int4*)(ei + E);
    int4 d = __ldg(&d4[i]);
    atomicAdd(&g_cnt[d.x], 1);
    atomicAdd(&g_cnt[d.y], 1);
    atomicAdd(&g_cnt[d.z], 1);
    atomicAdd(&g_cnt[d.w], 1);
}

// ================= k_scan =================
__global__ void k_scan() {
    __shared__ int sh[256];
    __shared__ int s_base;
    const int b = blockIdx.x, t = threadIdx.x;
    const int i0 = b * 1024 + t * 4;

    int v0 = (i0 + 0 < N) ? __ldcg(&g_cnt[i0 + 0]) : 0;
    int v1 = (i0 + 1 < N) ? __ldcg(&g_cnt[i0 + 1]) : 0;
    int v2 = (i0 + 2 < N) ? __ldcg(&g_cnt[i0 + 2]) : 0;
    int v3 = (i0 + 3 < N) ? __ldcg(&g_cnt[i0 + 3]) : 0;
    int tot = v0 + v1 + v2 + v3;

    sh[t] = tot;
    if (t == 0) s_base = 0;
    __syncthreads();
#pragma unroll
    for (int o = 1; o < 256; o <<= 1) {
        int a = (t >= o) ? sh[t - o] : 0;
        __syncthreads();
        sh[t] += a;
        __syncthreads();
    }
    int incl = sh[t];
    if (t == 255) {
        g_aggA[b] = incl;
        __threadfence();
        atomicAdd(&g_ready, 1);
    }
    if (t == 0) {
        while (__ldcg((const int*)&g_ready) < SCAN_BLOCKS) __nanosleep(32);
    }
    __syncthreads();
    if (t < b) atomicAdd(&s_base, __ldcg(&g_aggA[t]));
    __syncthreads();

    int e0 = s_base + incl - tot;
    int pre[4] = {e0, e0 + v0, e0 + v0 + v1, e0 + v0 + v1 + v2};
    int vv[4]  = {v0, v1, v2, v3};
#pragma unroll
    for (int u = 0; u < 4; ++u) {
        int i = i0 + u;
        if (i < N) {
            g_rowptr[i] = pre[u];
            g_cur[i]    = pre[u];
            g_dinv[i]   = rsqrtf((float)(vv[u] + 1));
            g_cnt[i]    = 0;
        }
    }
    if (b == 0 && t == 0) g_rowptr[N] = E;
}

// ====== k2: register-tiled GEMM (4 rows x 8 cols / thread) || scatter — R10 version ======
__global__ void __launch_bounds__(128, 4) k2(
    const float* __restrict__ x, const float* __restrict__ W1,
    const int* __restrict__ ei)
{
    extern __shared__ float sm[];
    const int t = threadIdx.x, bid = blockIdx.x;

    if (bid < GB) {
        const float4* w4 = (const float4*)W1;
        float4* s4 = (float4*)sm;
#pragma unroll
        for (int i = 0; i < 16; ++i) s4[i * 128 + t] = __ldg(&w4[i * 128 + t]);

        float* xs = sm + 8192;                 // 256 rows x XS_STRIDE
        const int row0 = bid * 256;
        const int c  = t & 1;                  // col half
        const int rg = t >> 1;                 // 0..63

        unsigned long long acc[4][4];
#pragma unroll
        for (int j = 0; j < 4; ++j)
#pragma unroll
            for (int p = 0; p < 4; ++p) acc[j][p] = 0ull;

        for (int kt = 0; kt < 64; ++kt) {
            __syncthreads();
#pragma unroll
            for (int p = 0; p < 4; ++p) {
                int idx = p * 128 + t;
                int row = idx >> 1, half = idx & 1;
                int gr = row0 + row; if (gr >= N) gr = N - 1;
                float4 v = __ldg((const float4*)(x + (size_t)gr * FIN + kt * 8 + half * 4));
                *(float4*)(xs + row * XS_STRIDE + half * 4) = v;
            }
            __syncthreads();
#pragma unroll
            for (int kh = 0; kh < 2; ++kh) {
                float xq[4][4];
#pragma unroll
                for (int j = 0; j < 4; ++j) {
                    float4 v = *(const float4*)(xs + (rg + 64 * j) * XS_STRIDE + kh * 4);
                    xq[j][0] = v.x; xq[j][1] = v.y; xq[j][2] = v.z; xq[j][3] = v.w;
                }
#pragma unroll
                for (int kk = 0; kk < 4; ++kk) {
                    int k = kt * 8 + kh * 4 + kk;
                    ulonglong2 w0 = *(const ulonglong2*)(sm + k * 16 + c * 8);
                    ulonglong2 w1 = *(const ulonglong2*)(sm + k * 16 + c * 8 + 4);
#pragma unroll
                    for (int j = 0; j < 4; ++j) {
                        unsigned long long b = bcast2(xq[j][kk]);
                        ffma2(acc[j][0], b, w0.x); ffma2(acc[j][1], b, w0.y);
                        ffma2(acc[j][2], b, w1.x); ffma2(acc[j][3], b, w1.y);
                    }
                }
            }
        }
#pragma unroll
        for (int j = 0; j < 4; ++j) {
            int row = row0 + rg + 64 * j;
            if (row < N) {
                float dv = g_dinv[row];
                float2 p0 = unpack2(acc[j][0]), p1 = unpack2(acc[j][1]);
                float2 p2 = unpack2(acc[j][2]), p3 = unpack2(acc[j][3]);
                uint2 lo = pack_h4(p0.x * dv, p0.y * dv, p1.x * dv, p1.y * dv);
                uint2 hi = pack_h4(p2.x * dv, p2.y * dv, p3.x * dv, p3.y * dv);
                ((uint4*)&g_h1h[(size_t)row * 4])[c] = make_uint4(lo.x, lo.y, hi.x, hi.y);
            }
        }
    } else {
        const int4* s4 = (const int4*)ei;
        const int4* d4 = (const int4*)(ei + E);
        const int nthr = SBK * 128;
        for (int i = (bid - GB) * 128 + t; i < E / 4; i += nthr) {
            int4 s = __ldg(&s4[i]);
            int4 d = __ldg(&d4[i]);
            g_csrc[atomicAdd(&g_cur[d.x], 1)] = s.x;
            g_csrc[atomicAdd(&g_cur[d.y], 1)] = s.y;
            g_csrc[atomicAdd(&g_cur[d.z], 1)] = s.z;
            g_csrc[atomicAdd(&g_cur[d.w], 1)] = s.w;
        }
    }
}

// ================= pair gather =================
__device__ __forceinline__ void gather_pair(const uint2* __restrict__ h,
                                            int sA, int eA, int eB,
                                            int lane, int slot, int q,
                                            float4& A, float4& B) {
    A = make_float4(0.f, 0.f, 0.f, 0.f);
    B = make_float4(0.f, 0.f, 0.f, 0.f);
    for (int base = sA; base < eB; base += 32) {
        int e = base + lane;
        int s = (e < eB) ? __ldg(&g_csrc[e]) : 0;
#pragma unroll
        for (int j = 0; j < 32; j += 8) {
            int jj = j + slot;
            int ee = base + jj;
            int sj = __shfl_sync(0xffffffffu, s, jj);
            if (ee < eB) {
                float4 v = h4_to_f4(__ldg(&h[(size_t)sj * 4 + q]));
                if (ee < eA) {
                    A.x += v.x; A.y += v.y; A.z += v.z; A.w += v.w;
                } else {
                    B.x += v.x; B.y += v.y; B.z += v.z; B.w += v.w;
                }
            }
        }
    }
#pragma unroll
    for (int o = 4; o < 32; o <<= 1) {
        A.x += __shfl_xor_sync(0xffffffffu, A.x, o);
        A.y += __shfl_xor_sync(0xffffffffu, A.y, o);
        A.z += __shfl_xor_sync(0xffffffffu, A.z, o);
        A.w += __shfl_xor_sync(0xffffffffu, A.w, o);
        B.x += __shfl_xor_sync(0xffffffffu, B.x, o);
        B.y += __shfl_xor_sync(0xffffffffu, B.y, o);
        B.z += __shfl_xor_sync(0xffffffffu, B.z, o);
        B.w += __shfl_xor_sync(0xffffffffu, B.w, o);
    }
}

// layer-1 epilogue (trivial): rs = relu((acc+self)*dinv + b1) * dinv
__device__ __forceinline__ uint2 epi1s(int node, float4 acc, float4 b1q, int q) {
    float dv = g_dinv[node];
    float4 sv = h4_to_f4(g_h1h[(size_t)node * 4 + q]);
    float rx = fmaxf((acc.x + sv.x) * dv + b1q.x, 0.f);
    float ry = fmaxf((acc.y + sv.y) * dv + b1q.y, 0.f);
    float rz = fmaxf((acc.z + sv.z) * dv + b1q.z, 0.f);
    float rw = fmaxf((acc.w + sv.w) * dv + b1q.w, 0.f);
    return pack_h4(rx * dv, ry * dv, rz * dv, rw * dv);
}

// ================= agg1 =================
__global__ void __launch_bounds__(256) k_agg1(const float* __restrict__ b1) {
    const int t = threadIdx.x;
    const int wid = (int)((blockIdx.x * blockDim.x + t) >> 5);
    const int nA = wid * 2;
    const int lane = t & 31, slot = lane >> 2, q = lane & 3;
    const float4 b1q = __ldg(&((const float4*)b1)[q]);

    const int sA = __ldg(&g_rowptr[nA]);
    const int eA = __ldg(&g_rowptr[nA + 1]);
    const int eB = __ldg(&g_rowptr[nA + 2]);

    float4 accA, accB;
    gather_pair(g_h1h, sA, eA, eB, lane, slot, q, accA, accB);

    uint2 oA = epi1s(nA, accA, b1q, q);
    if (slot == 0) g_rsh[(size_t)nA * 4 + q] = oA;
    uint2 oB = epi1s(nA + 1, accB, b1q, q);
    if (slot == 1) g_rsh[(size_t)(nA + 1) * 4 + q] = oB;
}

// ================= k_w2: rs2 = W2^T rs, per node (linearity) =================
__global__ void __launch_bounds__(256) k_w2() {
    __shared__ float w2s[256];     // W2[k][c], row-major 16x16
    const int t = threadIdx.x;
    // W2 loaded via global const pointer passed in — stored in cbank instead:
    // (W2 passed as kernel arg below)
    extern __shared__ float dummy[];
    (void)dummy;
    const int node = blockIdx.x * 256 + t;
    if (node >= N) return;
    // placeholder; real body in k_w2_impl
}

// real k_w2 (takes W2 pointer)
__global__ void __launch_bounds__(256) k_w2x(const float* __restrict__ W2) {
    __shared__ float w2s[256];
    const int t = threadIdx.x;
    if (t < 256) w2s[t] = __ldg(&W2[t]);
    __syncthreads();

    const int node = blockIdx.x * 256 + t;
    if (node >= N) return;

    const uint2* src = &g_rsh[(size_t)node * 4];
    uint2 r0 = src[0], r1 = src[1], r2 = src[2], r3 = src[3];
    float4 a0 = h4_to_f4(r0), a1 = h4_to_f4(r1);
    float4 a2 = h4_to_f4(r2), a3 = h4_to_f4(r3);
    float rs[16] = {a0.x, a0.y, a0.z, a0.w, a1.x, a1.y, a1.z, a1.w,
                    a2.x, a2.y, a2.z, a2.w, a3.x, a3.y, a3.z, a3.w};
    float h2[16];
#pragma unroll
    for (int cc = 0; cc < 16; ++cc) h2[cc] = 0.f;
#pragma unroll
    for (int k = 0; k < 16; ++k) {
        float rk = rs[k];
#pragma unroll
        for (int cc = 0; cc < 16; ++cc)
            h2[cc] = fmaf(rk, w2s[k * 16 + cc], h2[cc]);
    }
    uint2 o0 = pack_h4(h2[0], h2[1], h2[2], h2[3]);
    uint2 o1 = pack_h4(h2[4], h2[5], h2[6], h2[7]);
    uint2 o2 = pack_h4(h2[8], h2[9], h2[10], h2[11]);
    uint2 o3 = pack_h4(h2[12], h2[13], h2[14], h2[15]);
    uint4* dst = (uint4*)&g_rs2h[(size_t)node * 4];
    dst[0] = make_uint4(o0.x, o0.y, o1.x, o1.y);
    dst[1] = make_uint4(o2.x, o2.y, o3.x, o3.y);
}

// layer-2 epilogue (trivial): val = (acc+self)*dinv + b2, log_softmax
__device__ __forceinline__ float4 epi2s(int node, float4 acc, float4 b2q, int q) {
    float dv = g_dinv[node];
    float4 sv = h4_to_f4(g_rs2h[(size_t)node * 4 + q]);
    float4 val;
    val.x = (acc.x + sv.x) * dv + b2q.x;
    val.y = (acc.y + sv.y) * dv + b2q.y;
    val.z = (acc.z + sv.z) * dv + b2q.z;
    val.w = (acc.w + sv.w) * dv + b2q.w;

    float m = fmaxf(fmaxf(val.x, val.y), fmaxf(val.z, val.w));
    m = fmaxf(m, __shfl_xor_sync(0xffffffffu, m, 1));
    m = fmaxf(m, __shfl_xor_sync(0xffffffffu, m, 2));
    float ssum = __expf(val.x - m) + __expf(val.y - m) +
                 __expf(val.z - m) + __expf(val.w - m);
    ssum += __shfl_xor_sync(0xffffffffu, ssum, 1);
    ssum += __shfl_xor_sync(0xffffffffu, ssum, 2);
    float lse = m + __logf(ssum);
    return make_float4(val.x - lse, val.y - lse, val.z - lse, val.w - lse);
}

// ================= agg2 =================
__global__ void __launch_bounds__(256) k_agg2(const float* __restrict__ b2,
                                              float* __restrict__ out) {
    const int t = threadIdx.x;
    const int wid = (int)((blockIdx.x * blockDim.x + t) >> 5);
    const int nA = wid * 2;
    const int lane = t & 31, slot = lane >> 2, q = lane & 3;
    const float4 b2q = __ldg(&((const float4*)b2)[q]);

    const int sA = __ldg(&g_rowptr[nA]);
    const int eA = __ldg(&g_rowptr[nA + 1]);
    const int eB = __ldg(&g_rowptr[nA + 2]);

    float4 accA, accB;
    gather_pair(g_rs2h, sA, eA, eB, lane, slot, q, accA, accB);

    float4 oA = epi2s(nA, accA, b2q, q);
    if (slot == 0) ((float4*)out)[(size_t)nA * 4 + q] = oA;
    float4 oB = epi2s(nA + 1, accB, b2q, q);
    if (slot == 1) ((float4*)out)[(size_t)(nA + 1) * 4 + q] = oB;
}

// ================= launch =================
extern "C" void kernel_launch(void* const* d_in, const int* in_sizes, int n_in,
                              void* d_out, int out_size) {
    const float* x  = (const float*)d_in[0];
    const float* W1 = (const float*)d_in[1];
    const float* b1 = (const float*)d_in[2];
    const float* W2 = (const float*)d_in[3];
    const float* b2 = (const float*)d_in[4];
    const int*   ei = (const int*)d_in[5];
    float* out = (float*)d_out;

    cudaFuncSetAttribute((const void*)k2,
                         cudaFuncAttributeMaxDynamicSharedMemorySize, SMEM_BYTES);

    k_hist<<<E / 4 / 256, 256>>>(ei);
    k_scan<<<SCAN_BLOCKS, 256>>>();
    k2    <<<GRID2, 128, SMEM_BYTES>>>(x, W1, ei);
    k_agg1<<<N / 2 / 8, 256>>>(b1);
    k_w2x <<<(N + 255) / 256, 256>>>(W2);
    k_agg2<<<N / 2 / 8, 256>>>(b2, out);
}

// round 13
// speedup vs baseline: 1.3939x; 1.0590x over previous
#include <cuda_runtime.h>
#include <cuda_fp16.h>

constexpr int N   = 100000;
constexpr int E   = 3200000;
constexpr int FIN = 512;
constexpr int SCAN_BLOCKS = 98;               // ceil(N/1024)
constexpr int GBM = (N + 127) / 128;          // 782 gemm blocks (128 rows each)
constexpr int SBK = 100;                      // scatter blocks (256 thr)
constexpr int GRID2 = GBM + SBK;              // 882
constexpr int WT_STRIDE = 520;                // halves per W1T row (pad for banks)

// scratch (zero-init at load; self-cleaned every run)
__device__ int    g_cnt[N];            // zeroed by k_scan after reading
__device__ int    g_aggA[SCAN_BLOCKS];
__device__ int    g_ready;             // reset by k_hist each run
__device__ int    g_rowptr[N + 1];
__device__ int    g_cur[N];
__device__ int    g_csrc[E];
__device__ float  g_dinv[N];
__device__ __align__(16) uint2 g_h1h[N * 4];   // fp16: h1 * dinv[row]
__device__ __align__(16) uint2 g_rsh[N * 4];   // fp16: relu(l1) * dinv[row]
__device__ __align__(16) uint2 g_rs2h[N * 4];  // fp16: (W2^T rs) rows

__device__ __forceinline__ float4 h4_to_f4(uint2 hv) {
    __half2 a = *reinterpret_cast<__half2*>(&hv.x);
    __half2 b = *reinterpret_cast<__half2*>(&hv.y);
    float2 fa = __half22float2(a);
    float2 fb = __half22float2(b);
    return make_float4(fa.x, fa.y, fb.x, fb.y);
}
__device__ __forceinline__ uint2 pack_h4(float a, float b, float c, float d) {
    __half2 lo = __floats2half2_rn(a, b);
    __half2 hi = __floats2half2_rn(c, d);
    uint2 r;
    r.x = *reinterpret_cast<unsigned*>(&lo);
    r.y = *reinterpret_cast<unsigned*>(&hi);
    return r;
}
__device__ __forceinline__ unsigned packh2(float a, float b) {
    __half2 h = __floats2half2_rn(a, b);
    return *reinterpret_cast<unsigned*>(&h);
}

// ================= k_hist =================
__global__ void k_hist(const int* __restrict__ ei) {
    if (blockIdx.x == 0 && threadIdx.x == 0) g_ready = 0;
    int i = blockIdx.x * blockDim.x + threadIdx.x;   // exactly E/4 threads
    const int4* d4 = (const int4*)(ei + E);
    int4 d = __ldg(&d4[i]);
    atomicAdd(&g_cnt[d.x], 1);
    atomicAdd(&g_cnt[d.y], 1);
    atomicAdd(&g_cnt[d.z], 1);
    atomicAdd(&g_cnt[d.w], 1);
}

// ================= k_scan =================
__global__ void k_scan() {
    __shared__ int sh[256];
    __shared__ int s_base;
    const int b = blockIdx.x, t = threadIdx.x;
    const int i0 = b * 1024 + t * 4;

    int v0 = (i0 + 0 < N) ? __ldcg(&g_cnt[i0 + 0]) : 0;
    int v1 = (i0 + 1 < N) ? __ldcg(&g_cnt[i0 + 1]) : 0;
    int v2 = (i0 + 2 < N) ? __ldcg(&g_cnt[i0 + 2]) : 0;
    int v3 = (i0 + 3 < N) ? __ldcg(&g_cnt[i0 + 3]) : 0;
    int tot = v0 + v1 + v2 + v3;

    sh[t] = tot;
    if (t == 0) s_base = 0;
    __syncthreads();
#pragma unroll
    for (int o = 1; o < 256; o <<= 1) {
        int a = (t >= o) ? sh[t - o] : 0;
        __syncthreads();
        sh[t] += a;
        __syncthreads();
    }
    int incl = sh[t];
    if (t == 255) {
        g_aggA[b] = incl;
        __threadfence();
        atomicAdd(&g_ready, 1);
    }
    if (t == 0) {
        while (__ldcg((const int*)&g_ready) < SCAN_BLOCKS) __nanosleep(32);
    }
    __syncthreads();
    if (t < b) atomicAdd(&s_base, __ldcg(&g_aggA[t]));
    __syncthreads();

    int e0 = s_base + incl - tot;
    int pre[4] = {e0, e0 + v0, e0 + v0 + v1, e0 + v0 + v1 + v2};
    int vv[4]  = {v0, v1, v2, v3};
#pragma unroll
    for (int u = 0; u < 4; ++u) {
        int i = i0 + u;
        if (i < N) {
            g_rowptr[i] = pre[u];
            g_cur[i]    = pre[u];
            g_dinv[i]   = rsqrtf((float)(vv[u] + 1));
            g_cnt[i]    = 0;
        }
    }
    if (b == 0 && t == 0) g_rowptr[N] = E;
}

// ====== k2: HMMA tensor-core GEMM (16 rows x 16 cols / warp) || scatter ======
__global__ void __launch_bounds__(256) k2(
    const float* __restrict__ x, const float* __restrict__ W1,
    const int* __restrict__ ei)
{
    __shared__ __half w1t[16 * WT_STRIDE];    // W1 transposed: [n][k], padded
    const int t = threadIdx.x, bid = blockIdx.x;

    if (bid < GBM) {
        // stage W1 transposed as fp16
        for (int idx = t; idx < FIN * 16; idx += 256) {
            int k = idx >> 4, n = idx & 15;
            w1t[n * WT_STRIDE + k] = __float2half(__ldg(&W1[idx]));
        }
        __syncthreads();

        const int warp = t >> 5, lane = t & 31;
        const int qr = lane >> 2;            // 0..7
        const int qk = (lane & 3) * 2;       // 0,2,4,6
        const int row0 = bid * 128 + warp * 16 + qr;   // thread's first row
        int r0 = row0, r1 = row0 + 8;
        if (r0 >= N) r0 = N - 1;
        if (r1 >= N) r1 = N - 1;

        const float* ap0 = x + (size_t)r0 * FIN + qk;
        const float* ap1 = x + (size_t)r1 * FIN + qk;
        const __half* bp = w1t + qr * WT_STRIDE + qk;  // n = qr

        float c0[4] = {0.f, 0.f, 0.f, 0.f};   // n-half 0 (cols 0..7)
        float c1[4] = {0.f, 0.f, 0.f, 0.f};   // n-half 1 (cols 8..15)

#pragma unroll 4
        for (int ks = 0; ks < FIN / 16; ++ks) {
            const int kb = ks * 16;
            float2 fa0 = __ldg((const float2*)(ap0 + kb));
            float2 fa2 = __ldg((const float2*)(ap0 + kb + 8));
            float2 fa1 = __ldg((const float2*)(ap1 + kb));
            float2 fa3 = __ldg((const float2*)(ap1 + kb + 8));
            unsigned a0 = packh2(fa0.x, fa0.y);
            unsigned a1 = packh2(fa1.x, fa1.y);
            unsigned a2 = packh2(fa2.x, fa2.y);
            unsigned a3 = packh2(fa3.x, fa3.y);
            // B fragments for n-half 0: n = qr (cols 0..7)
            unsigned b0 = *(const unsigned*)(bp + kb);
            unsigned b1 = *(const unsigned*)(bp + kb + 8);
            // B fragments for n-half 1: n = qr + 8
            unsigned b2 = *(const unsigned*)(bp + 8 * WT_STRIDE + kb);
            unsigned b3 = *(const unsigned*)(bp + 8 * WT_STRIDE + kb + 8);
            asm("mma.sync.aligned.m16n8k16.row.col.f32.f16.f16.f32 "
                "{%0,%1,%2,%3}, {%4,%5,%6,%7}, {%8,%9}, {%0,%1,%2,%3};"
                : "+f"(c0[0]), "+f"(c0[1]), "+f"(c0[2]), "+f"(c0[3])
                : "r"(a0), "r"(a1), "r"(a2), "r"(a3), "r"(b0), "r"(b1));
            asm("mma.sync.aligned.m16n8k16.row.col.f32.f16.f16.f32 "
                "{%0,%1,%2,%3}, {%4,%5,%6,%7}, {%8,%9}, {%0,%1,%2,%3};"
                : "+f"(c1[0]), "+f"(c1[1]), "+f"(c1[2]), "+f"(c1[3])
                : "r"(a0), "r"(a1), "r"(a2), "r"(a3), "r"(b2), "r"(b3));
        }
        // epilogue: C[r][c] -> g_h1h (fp16, *dinv). Thread owns rows row0, row0+8,
        // cols qk,qk+1 (half 0) and qk+8,qk+9 (half 1).
        {
            int rA = row0;
            if (rA < N) {
                float dv = g_dinv[rA];
                unsigned* dst = (unsigned*)&g_h1h[(size_t)rA * 4];
                dst[(qk >> 1)]     = packh2(c0[0] * dv, c0[1] * dv);
                dst[(qk >> 1) + 4] = packh2(c1[0] * dv, c1[1] * dv);
            }
            int rB = row0 + 8;
            if (rB < N) {
                float dv = g_dinv[rB];
                unsigned* dst = (unsigned*)&g_h1h[(size_t)rB * 4];
                dst[(qk >> 1)]     = packh2(c0[2] * dv, c0[3] * dv);
                dst[(qk >> 1) + 4] = packh2(c1[2] * dv, c1[3] * dv);
            }
        }
    } else {
        // scatter: fill CSR adjacency
        const int4* s4 = (const int4*)ei;
        const int4* d4 = (const int4*)(ei + E);
        const int nthr = SBK * 256;
        for (int i = (bid - GBM) * 256 + t; i < E / 4; i += nthr) {
            int4 s = __ldg(&s4[i]);
            int4 d = __ldg(&d4[i]);
            g_csrc[atomicAdd(&g_cur[d.x], 1)] = s.x;
            g_csrc[atomicAdd(&g_cur[d.y], 1)] = s.y;
            g_csrc[atomicAdd(&g_cur[d.z], 1)] = s.z;
            g_csrc[atomicAdd(&g_cur[d.w], 1)] = s.w;
        }
    }
}

// ================= pair gather =================
__device__ __forceinline__ void gather_pair(const uint2* __restrict__ h,
                                            int sA, int eA, int eB,
                                            int lane, int slot, int q,
                                            float4& A, float4& B) {
    A = make_float4(0.f, 0.f, 0.f, 0.f);
    B = make_float4(0.f, 0.f, 0.f, 0.f);
    for (int base = sA; base < eB; base += 32) {
        int e = base + lane;
        int s = (e < eB) ? __ldg(&g_csrc[e]) : 0;
#pragma unroll
        for (int j = 0; j < 32; j += 8) {
            int jj = j + slot;
            int ee = base + jj;
            int sj = __shfl_sync(0xffffffffu, s, jj);
            if (ee < eB) {
                float4 v = h4_to_f4(__ldg(&h[(size_t)sj * 4 + q]));
                if (ee < eA) {
                    A.x += v.x; A.y += v.y; A.z += v.z; A.w += v.w;
                } else {
                    B.x += v.x; B.y += v.y; B.z += v.z; B.w += v.w;
                }
            }
        }
    }
#pragma unroll
    for (int o = 4; o < 32; o <<= 1) {
        A.x += __shfl_xor_sync(0xffffffffu, A.x, o);
        A.y += __shfl_xor_sync(0xffffffffu, A.y, o);
        A.z += __shfl_xor_sync(0xffffffffu, A.z, o);
        A.w += __shfl_xor_sync(0xffffffffu, A.w, o);
        B.x += __shfl_xor_sync(0xffffffffu, B.x, o);
        B.y += __shfl_xor_sync(0xffffffffu, B.y, o);
        B.z += __shfl_xor_sync(0xffffffffu, B.z, o);
        B.w += __shfl_xor_sync(0xffffffffu, B.w, o);
    }
}

// layer-1 epilogue (trivial): rs = relu((acc+self)*dinv + b1) * dinv
__device__ __forceinline__ uint2 epi1s(int node, float4 acc, float4 b1q, int q) {
    float dv = g_dinv[node];
    float4 sv = h4_to_f4(g_h1h[(size_t)node * 4 + q]);
    float rx = fmaxf((acc.x + sv.x) * dv + b1q.x, 0.f);
    float ry = fmaxf((acc.y + sv.y) * dv + b1q.y, 0.f);
    float rz = fmaxf((acc.z + sv.z) * dv + b1q.z, 0.f);
    float rw = fmaxf((acc.w + sv.w) * dv + b1q.w, 0.f);
    return pack_h4(rx * dv, ry * dv, rz * dv, rw * dv);
}

// ================= agg1 =================
__global__ void __launch_bounds__(256) k_agg1(const float* __restrict__ b1) {
    const int t = threadIdx.x;
    const int wid = (int)((blockIdx.x * blockDim.x + t) >> 5);
    const int nA = wid * 2;
    const int lane = t & 31, slot = lane >> 2, q = lane & 3;
    const float4 b1q = __ldg(&((const float4*)b1)[q]);

    const int sA = __ldg(&g_rowptr[nA]);
    const int eA = __ldg(&g_rowptr[nA + 1]);
    const int eB = __ldg(&g_rowptr[nA + 2]);

    float4 accA, accB;
    gather_pair(g_h1h, sA, eA, eB, lane, slot, q, accA, accB);

    uint2 oA = epi1s(nA, accA, b1q, q);
    if (slot == 0) g_rsh[(size_t)nA * 4 + q] = oA;
    uint2 oB = epi1s(nA + 1, accB, b1q, q);
    if (slot == 1) g_rsh[(size_t)(nA + 1) * 4 + q] = oB;
}

// ================= k_w2: rs2 = W2^T rs, per node (linearity) =================
__global__ void __launch_bounds__(256) k_w2x(const float* __restrict__ W2) {
    __shared__ float w2s[256];
    const int t = threadIdx.x;
    if (t < 256) w2s[t] = __ldg(&W2[t]);
    __syncthreads();

    const int node = blockIdx.x * 256 + t;
    if (node >= N) return;

    const uint2* src = &g_rsh[(size_t)node * 4];
    uint2 r0 = src[0], r1 = src[1], r2 = src[2], r3 = src[3];
    float4 a0 = h4_to_f4(r0), a1 = h4_to_f4(r1);
    float4 a2 = h4_to_f4(r2), a3 = h4_to_f4(r3);
    float rs[16] = {a0.x, a0.y, a0.z, a0.w, a1.x, a1.y, a1.z, a1.w,
                    a2.x, a2.y, a2.z, a2.w, a3.x, a3.y, a3.z, a3.w};
    float h2[16];
#pragma unroll
    for (int cc = 0; cc < 16; ++cc) h2[cc] = 0.f;
#pragma unroll
    for (int k = 0; k < 16; ++k) {
        float rk = rs[k];
#pragma unroll
        for (int cc = 0; cc < 16; ++cc)
            h2[cc] = fmaf(rk, w2s[k * 16 + cc], h2[cc]);
    }
    uint2 o0 = pack_h4(h2[0], h2[1], h2[2], h2[3]);
    uint2 o1 = pack_h4(h2[4], h2[5], h2[6], h2[7]);
    uint2 o2 = pack_h4(h2[8], h2[9], h2[10], h2[11]);
    uint2 o3 = pack_h4(h2[12], h2[13], h2[14], h2[15]);
    uint4* dst = (uint4*)&g_rs2h[(size_t)node * 4];
    dst[0] = make_uint4(o0.x, o0.y, o1.x, o1.y);
    dst[1] = make_uint4(o2.x, o2.y, o3.x, o3.y);
}

// layer-2 epilogue (trivial): val = (acc+self)*dinv + b2, log_softmax
__device__ __forceinline__ float4 epi2s(int node, float4 acc, float4 b2q, int q) {
    float dv = g_dinv[node];
    float4 sv = h4_to_f4(g_rs2h[(size_t)node * 4 + q]);
    float4 val;
    val.x = (acc.x + sv.x) * dv + b2q.x;
    val.y = (acc.y + sv.y) * dv + b2q.y;
    val.z = (acc.z + sv.z) * dv + b2q.z;
    val.w = (acc.w + sv.w) * dv + b2q.w;

    float m = fmaxf(fmaxf(val.x, val.y), fmaxf(val.z, val.w));
    m = fmaxf(m, __shfl_xor_sync(0xffffffffu, m, 1));
    m = fmaxf(m, __shfl_xor_sync(0xffffffffu, m, 2));
    float ssum = __expf(val.x - m) + __expf(val.y - m) +
                 __expf(val.z - m) + __expf(val.w - m);
    ssum += __shfl_xor_sync(0xffffffffu, ssum, 1);
    ssum += __shfl_xor_sync(0xffffffffu, ssum, 2);
    float lse = m + __logf(ssum);
    return make_float4(val.x - lse, val.y - lse, val.z - lse, val.w - lse);
}

// ================= agg2 =================
__global__ void __launch_bounds__(256) k_agg2(const float* __restrict__ b2,
                                              float* __restrict__ out) {
    const int t = threadIdx.x;
    const int wid = (int)((blockIdx.x * blockDim.x + t) >> 5);
    const int nA = wid * 2;
    const int lane = t & 31, slot = lane >> 2, q = lane & 3;
    const float4 b2q = __ldg(&((const float4*)b2)[q]);

    const int sA = __ldg(&g_rowptr[nA]);
    const int eA = __ldg(&g_rowptr[nA + 1]);
    const int eB = __ldg(&g_rowptr[nA + 2]);

    float4 accA, accB;
    gather_pair(g_rs2h, sA, eA, eB, lane, slot, q, accA, accB);

    float4 oA = epi2s(nA, accA, b2q, q);
    if (slot == 0) ((float4*)out)[(size_t)nA * 4 + q] = oA;
    float4 oB = epi2s(nA + 1, accB, b2q, q);
    if (slot == 1) ((float4*)out)[(size_t)(nA + 1) * 4 + q] = oB;
}

// ================= launch =================
extern "C" void kernel_launch(void* const* d_in, const int* in_sizes, int n_in,
                              void* d_out, int out_size) {
    const float* x  = (const float*)d_in[0];
    const float* W1 = (const float*)d_in[1];
    const float* b1 = (const float*)d_in[2];
    const float* W2 = (const float*)d_in[3];
    const float* b2 = (const float*)d_in[4];
    const int*   ei = (const int*)d_in[5];
    float* out = (float*)d_out;

    k_hist<<<E / 4 / 256, 256>>>(ei);
    k_scan<<<SCAN_BLOCKS, 256>>>();
    k2    <<<GRID2, 256>>>(x, W1, ei);
    k_agg1<<<N / 2 / 8, 256>>>(b1);
    k_w2x <<<(N + 255) / 256, 256>>>(W2);
    k_agg2<<<N / 2 / 8, 256>>>(b2, out);
}